// round 4
// baseline (speedup 1.0000x reference)
#include <cuda_runtime.h>
#include <math.h>
#include <stdint.h>

#define SEQ 1024
#define BB  64
#define DD  512
#define HH  512

#define NCTA0 32
#define NSL0  16   // cols per layer-0 CTA
#define NCTA1 64
#define NSL1  8    // cols per layer-1 CTA

#define HSS 516    // padded shared row stride (floats) for h

typedef unsigned long long u64;

// Scratch (allocation-free rule: __device__ globals)
__device__ float g_z0[SEQ * BB * HH];   // x@Wx0 + bx0 + bh0
__device__ float g_h0[SEQ * BB * HH];   // layer-0 hidden history
__device__ int   g_flag0[SEQ];
__device__ int   g_flag1[SEQ];

// ---------------------------------------------------------------- helpers
__device__ __forceinline__ int ld_acq(const int* p) {
    int v;
    asm volatile("ld.acquire.gpu.s32 %0, [%1];" : "=r"(v) : "l"(p) : "memory");
    return v;
}
__device__ __forceinline__ u64 dup2(float x) {
    u64 r;
    asm("mov.b64 %0, {%1, %1};" : "=l"(r) : "f"(x));
    return r;
}
__device__ __forceinline__ void fma2(u64& acc, u64 a, u64 b) {
    asm("fma.rn.f32x2 %0, %1, %2, %0;" : "+l"(acc) : "l"(a), "l"(b));
}
__device__ __forceinline__ u64 add2(u64 a, u64 b) {
    u64 r;
    asm("add.rn.f32x2 %0, %1, %2;" : "=l"(r) : "l"(a), "l"(b));
    return r;
}
__device__ __forceinline__ float2 unp2(u64 v) {
    float2 f;
    asm("mov.b64 {%0, %1}, %2;" : "=f"(f.x), "=f"(f.y) : "l"(v));
    return f;
}
__device__ __forceinline__ void cp16(uint32_t s, const void* g) {
    asm volatile("cp.async.cg.shared.global [%0], [%1], 16;" :: "r"(s), "l"(g));
}
__device__ __forceinline__ void cp_commit() {
    asm volatile("cp.async.commit_group;" ::: "memory");
}
#define CP_WAIT(N) asm volatile("cp.async.wait_group %0;" :: "n"(N) : "memory")

// Issue one 128-k chunk (64 rows x 128 floats = 32KB) of h staging. 8 cp16/thread.
__device__ __forceinline__ void stage_chunk(uint32_t s0, const float* src, int c, int tid) {
    const float* sc = src + c * 128;
    uint32_t d0 = s0 + (uint32_t)(c * 128) * 4u;
#pragma unroll
    for (int j = 0; j < 8; j++) {
        int id = tid + j * 256;          // 0..2047
        int b  = id >> 5;                // row 0..63
        int kq = (id & 31) << 2;         // 0..124 step 4
        cp16(d0 + (uint32_t)(b * HSS + kq) * 4u, sc + (size_t)b * HH + kq);
    }
    cp_commit();
}

// Packed-fp32 GEMV: 2 batch rows x 2 cols, one 128-k chunk.
// acc[0]/acc[2]: row b0 (even/odd k);  acc[1]/acc[3]: row b1.
template<int NS>
__device__ __forceinline__ void gemv22(u64 acc[4], const float* hr0, const float* hr1,
                                       const float* wcol, int kbeg)
{
#pragma unroll 8
    for (int k = kbeg; k < kbeg + 128; k += 4) {
        float4 h0 = *(const float4*)(hr0 + k);
        float4 h1 = *(const float4*)(hr1 + k);
        u64 w0 = *(const u64*)(wcol + (size_t)(k + 0) * NS);
        u64 w1 = *(const u64*)(wcol + (size_t)(k + 1) * NS);
        u64 w2 = *(const u64*)(wcol + (size_t)(k + 2) * NS);
        u64 w3 = *(const u64*)(wcol + (size_t)(k + 3) * NS);
        u64 d;
        d = dup2(h0.x); fma2(acc[0], d, w0);
        d = dup2(h1.x); fma2(acc[1], d, w0);
        d = dup2(h0.y); fma2(acc[2], d, w1);
        d = dup2(h1.y); fma2(acc[3], d, w1);
        d = dup2(h0.z); fma2(acc[0], d, w2);
        d = dup2(h1.z); fma2(acc[1], d, w2);
        d = dup2(h0.w); fma2(acc[2], d, w3);
        d = dup2(h1.w); fma2(acc[3], d, w3);
    }
}

// ---------------------------------------------------------------------------
// Precompute Z0 = X @ Wx0 + bx0 + bh0 (packed fp32 inner) + zero the flags.
// ---------------------------------------------------------------------------
__global__ __launch_bounds__(256) void precompute_z0(
    const float* __restrict__ X,
    const float* __restrict__ W,
    const float* __restrict__ bxv,
    const float* __restrict__ bhv)
{
    __shared__ float As[16][64];
    __shared__ float Bs[16][64];
    const int tid = threadIdx.x;

    if (blockIdx.y == 0 && blockIdx.x < 4) {
        int i = blockIdx.x * 256 + tid;     // 0..1023
        g_flag0[i] = 0;
        g_flag1[i] = 0;
    }

    const int tx = tid & 15;
    const int ty = tid >> 4;
    const int m0 = blockIdx.x * 64;
    const int n0 = blockIdx.y * 64;
    const int lm = tid >> 2;
    const int lk = (tid & 3) << 2;
    const int lr = tid >> 4;
    const int lc = (tid & 15) << 2;

    u64 acc[4][2];
#pragma unroll
    for (int i = 0; i < 4; i++) { acc[i][0] = 0ULL; acc[i][1] = 0ULL; }

    for (int kc = 0; kc < DD; kc += 16) {
        float4 a4 = *(const float4*)(X + (size_t)(m0 + lm) * DD + kc + lk);
        float4 b4 = *(const float4*)(W + (size_t)(kc + lr) * HH + n0 + lc);
        As[lk + 0][lm] = a4.x;
        As[lk + 1][lm] = a4.y;
        As[lk + 2][lm] = a4.z;
        As[lk + 3][lm] = a4.w;
        *(float4*)&Bs[lr][lc] = b4;
        __syncthreads();
#pragma unroll
        for (int kk = 0; kk < 16; kk++) {
            float4 av = *(const float4*)&As[kk][ty << 2];
            ulonglong2 bq = *(const ulonglong2*)&Bs[kk][tx << 2];
            u64 d;
            d = dup2(av.x); fma2(acc[0][0], d, bq.x); fma2(acc[0][1], d, bq.y);
            d = dup2(av.y); fma2(acc[1][0], d, bq.x); fma2(acc[1][1], d, bq.y);
            d = dup2(av.z); fma2(acc[2][0], d, bq.x); fma2(acc[2][1], d, bq.y);
            d = dup2(av.w); fma2(acc[3][0], d, bq.x); fma2(acc[3][1], d, bq.y);
        }
        __syncthreads();
    }
    const int n = n0 + (tx << 2);
    float4 bx4 = *(const float4*)(bxv + n);
    float4 bh4 = *(const float4*)(bhv + n);
#pragma unroll
    for (int i = 0; i < 4; i++) {
        int m = m0 + (ty << 2) + i;
        float2 c0 = unp2(acc[i][0]);
        float2 c1 = unp2(acc[i][1]);
        float4 o;
        o.x = c0.x + bx4.x + bh4.x;
        o.y = c0.y + bx4.y + bh4.y;
        o.z = c1.x + bx4.z + bh4.z;
        o.w = c1.y + bx4.w + bh4.w;
        *(float4*)(g_z0 + (size_t)m * HH + n) = o;
    }
}

// ---------------------------------------------------------------------------
// Persistent sequential kernel. 96 CTAs (1/SM), 256 threads each.
//   blocks [0,32):  layer 0, 16-col slice, all threads full K=512, 2b x 2c tile.
//   blocks [32,96): layer 1, 8-col slice; warps 0-3 do h0[t]@Wx1 (phase B),
//                   warps 4-7 do h1[t-1]@Wh1 (phase A, overlapped with layer 0).
// Staging: 4 K-chunks via cp.async commit groups, overlapped with FMA.
// ---------------------------------------------------------------------------
__global__ __launch_bounds__(256) void rnn_seq(
    const float* __restrict__ h_init,
    const float* __restrict__ Wh0,
    const float* __restrict__ Wx1,
    const float* __restrict__ bx1,
    const float* __restrict__ Wh1,
    const float* __restrict__ bh1,
    float* __restrict__ out)
{
    extern __shared__ float sm[];
    float* hs = sm;                           // [64][HSS]
    float* ws = sm + 64 * HSS;                // 8192 floats of weights
    u64*  red = (u64*)(ws + 8192);            // 256 u64 (layer-1 reduction)
    const int tid = threadIdx.x;
    const uint32_t s0 = (uint32_t)__cvta_generic_to_shared(hs);

    if (blockIdx.x < NCTA0) {
        // ------------------------- layer 0 -------------------------
        const int n0 = blockIdx.x * NSL0;
        for (int i = tid; i < 512 * NSL0 / 4; i += 256) {
            int k = i >> 2, j = (i & 3) << 2;
            *(float4*)&ws[k * NSL0 + j] = *(const float4*)(Wh0 + (size_t)k * HH + n0 + j);
        }
        const int nq = tid & 7;               // col pair 0..7
        const int b0 = (tid >> 3) << 1;       // batch row 0..62 (even)
        const float* wcol = ws + nq * 2;
        const float* hr0 = hs + b0 * HSS;
        const float* hr1 = hr0 + HSS;

        for (int t = 0; t < SEQ; t++) {
            if (t > 0 && tid == 0) {
                while (ld_acq(&g_flag0[t - 1]) < NCTA0) {}
            }
            __syncthreads();
            const float* hp = (t == 0) ? h_init : (g_h0 + (size_t)(t - 1) * BB * HH);
            stage_chunk(s0, hp, 0, tid);
            stage_chunk(s0, hp, 1, tid);
            stage_chunk(s0, hp, 2, tid);
            stage_chunk(s0, hp, 3, tid);

            // z slice prefetch (independent of flags; consumed at epilogue)
            const float* z = g_z0 + (size_t)t * BB * HH + n0 + nq * 2;
            float2 z0v = *(const float2*)(z + (size_t)b0 * HH);
            float2 z1v = *(const float2*)(z + (size_t)(b0 + 1) * HH);

            u64 acc[4] = {0ULL, 0ULL, 0ULL, 0ULL};
            CP_WAIT(3); __syncthreads(); gemv22<NSL0>(acc, hr0, hr1, wcol, 0);
            CP_WAIT(2); __syncthreads(); gemv22<NSL0>(acc, hr0, hr1, wcol, 128);
            CP_WAIT(1); __syncthreads(); gemv22<NSL0>(acc, hr0, hr1, wcol, 256);
            CP_WAIT(0); __syncthreads(); gemv22<NSL0>(acc, hr0, hr1, wcol, 384);

            float2 p0 = unp2(add2(acc[0], acc[2]));
            float2 p1 = unp2(add2(acc[1], acc[3]));
            float2 v0, v1;
            v0.x = tanhf(p0.x + z0v.x); v0.y = tanhf(p0.y + z0v.y);
            v1.x = tanhf(p1.x + z1v.x); v1.y = tanhf(p1.y + z1v.y);
            float* ho = g_h0 + (size_t)t * BB * HH + n0 + nq * 2;
            *(float2*)(ho + (size_t)b0 * HH)       = v0;
            *(float2*)(ho + (size_t)(b0 + 1) * HH) = v1;
            if (t == SEQ - 1) {
                float* hn = out + (size_t)SEQ * BB * HH + n0 + nq * 2;
                *(float2*)(hn + (size_t)b0 * HH)       = v0;
                *(float2*)(hn + (size_t)(b0 + 1) * HH) = v1;
            }
            __syncthreads();
            if (tid == 0) { __threadfence(); atomicAdd(&g_flag0[t], 1); }
        }
    } else {
        // ------------------------- layer 1 -------------------------
        const int n0 = (blockIdx.x - NCTA0) * NSL1;
        float* wsx = ws;                       // [512][8]
        float* wsh = ws + 512 * NSL1;          // [512][8]
        for (int i = tid; i < 512 * NSL1 / 4; i += 256) {
            int k = i >> 1, j = (i & 1) << 2;
            *(float4*)&wsx[k * NSL1 + j] = *(const float4*)(Wx1 + (size_t)k * HH + n0 + j);
            *(float4*)&wsh[k * NSL1 + j] = *(const float4*)(Wh1 + (size_t)k * HH + n0 + j);
        }
        const int role = tid >> 7;             // 0: Wx1/h0[t], 1: Wh1/h1[t-1]
        const int nq   = tid & 3;              // col pair 0..3
        const int b0   = ((tid >> 2) & 31) << 1;
        const float* wcolx = wsx + nq * 2;
        const float* wcolh = wsh + nq * 2;
        const float* hr0 = hs + b0 * HSS;
        const float* hr1 = hr0 + HSS;
        u64* myred = red + (tid & 127) * 2;

        const float bb0 = bx1[n0 + nq * 2]     + bh1[n0 + nq * 2];
        const float bb1 = bx1[n0 + nq * 2 + 1] + bh1[n0 + nq * 2 + 1];

        for (int t = 0; t < SEQ; t++) {
            if (t > 0 && tid == 0) {
                while (ld_acq(&g_flag1[t - 1]) < NCTA1) {}
            }
            __syncthreads();

            // phase A: h1[t-1] @ Wh1 (role 1 computes; runs in layer-0's shadow)
            const float* hq = (t == 0) ? (h_init + BB * HH)
                                       : (out + (size_t)(t - 1) * BB * HH);
            stage_chunk(s0, hq, 0, tid);
            stage_chunk(s0, hq, 1, tid);
            stage_chunk(s0, hq, 2, tid);
            stage_chunk(s0, hq, 3, tid);

            u64 acc[4] = {0ULL, 0ULL, 0ULL, 0ULL};
            CP_WAIT(3); __syncthreads(); if (role) gemv22<NSL1>(acc, hr0, hr1, wcolh, 0);
            CP_WAIT(2); __syncthreads(); if (role) gemv22<NSL1>(acc, hr0, hr1, wcolh, 128);
            CP_WAIT(1); __syncthreads(); if (role) gemv22<NSL1>(acc, hr0, hr1, wcolh, 256);
            CP_WAIT(0); __syncthreads(); if (role) gemv22<NSL1>(acc, hr0, hr1, wcolh, 384);
            if (role) {
                myred[0] = add2(acc[0], acc[2]);
                myred[1] = add2(acc[1], acc[3]);
            }

            // phase B: h0[t] @ Wx1 (role 0 computes) — the critical tail
            if (tid == 0) {
                while (ld_acq(&g_flag0[t]) < NCTA0) {}
            }
            __syncthreads();                   // publishes red + orders acquire
            const float* hp = g_h0 + (size_t)t * BB * HH;
            stage_chunk(s0, hp, 0, tid);
            stage_chunk(s0, hp, 1, tid);
            stage_chunk(s0, hp, 2, tid);
            stage_chunk(s0, hp, 3, tid);

            u64 accb[4] = {0ULL, 0ULL, 0ULL, 0ULL};
            CP_WAIT(3); __syncthreads(); if (!role) gemv22<NSL1>(accb, hr0, hr1, wcolx, 0);
            CP_WAIT(2); __syncthreads(); if (!role) gemv22<NSL1>(accb, hr0, hr1, wcolx, 128);
            CP_WAIT(1); __syncthreads(); if (!role) gemv22<NSL1>(accb, hr0, hr1, wcolx, 256);
            CP_WAIT(0); __syncthreads(); if (!role) gemv22<NSL1>(accb, hr0, hr1, wcolx, 384);

            if (!role) {
                float2 p0 = unp2(add2(add2(accb[0], accb[2]), myred[0]));
                float2 p1 = unp2(add2(add2(accb[1], accb[3]), myred[1]));
                float2 v0, v1;
                v0.x = tanhf(p0.x + bb0); v0.y = tanhf(p0.y + bb1);
                v1.x = tanhf(p1.x + bb0); v1.y = tanhf(p1.y + bb1);
                float* o = out + (size_t)t * BB * HH + n0 + nq * 2;
                *(float2*)(o + (size_t)b0 * HH)       = v0;
                *(float2*)(o + (size_t)(b0 + 1) * HH) = v1;
                if (t == SEQ - 1) {
                    float* hn = out + (size_t)SEQ * BB * HH + BB * HH + n0 + nq * 2;
                    *(float2*)(hn + (size_t)b0 * HH)       = v0;
                    *(float2*)(hn + (size_t)(b0 + 1) * HH) = v1;
                }
            }
            __syncthreads();
            if (tid == 0) { __threadfence(); atomicAdd(&g_flag1[t], 1); }
        }
    }
}

#define SMEM_BYTES ((64 * HSS + 8192) * (int)sizeof(float) + 256 * 8)

extern "C" void kernel_launch(void* const* d_in, const int* in_sizes, int n_in,
                              void* d_out, int out_size)
{
    const float* x   = (const float*)d_in[0];
    const float* h0  = (const float*)d_in[1];
    const float* Wx0 = (const float*)d_in[2];
    const float* bx0 = (const float*)d_in[3];
    const float* Wh0 = (const float*)d_in[4];
    const float* bh0 = (const float*)d_in[5];
    const float* Wx1 = (const float*)d_in[6];
    const float* bx1 = (const float*)d_in[7];
    const float* Wh1 = (const float*)d_in[8];
    const float* bh1 = (const float*)d_in[9];
    float* out = (float*)d_out;
    (void)in_sizes; (void)n_in; (void)out_size;

    dim3 gz((SEQ * BB) / 64, HH / 64);
    precompute_z0<<<gz, 256>>>(x, Wx0, bx0, bh0);

    static int attr_set = 0;
    if (!attr_set) {
        cudaFuncSetAttribute(rnn_seq, cudaFuncAttributeMaxDynamicSharedMemorySize,
                             SMEM_BYTES);
        attr_set = 1;
    }
    rnn_seq<<<NCTA0 + NCTA1, 256, SMEM_BYTES>>>(h0, Wh0, Wx1, bx1, Wh1, bh1, out);
}

// round 5
// speedup vs baseline: 1.0847x; 1.0847x over previous
#include <cuda_runtime.h>
#include <math.h>
#include <stdint.h>

#define SEQ 1024
#define BB  64
#define DD  512
#define HH  512

#define NCTA0 32   // layer-0 CTAs, 16 cols each
#define NCTA1 64   // layer-1 CTAs, 8 cols each

typedef unsigned long long u64;

// Scratch (allocation-free rule: __device__ globals)
__device__ float g_z0 [SEQ * BB * HH];        // x@Wx0 + bx0 + bh0  (b-major)
__device__ float g_h0T[(SEQ + 1) * BB * HH];  // layer-0 h, TRANSPOSED [t][k][b]
__device__ float g_h1T[(SEQ + 1) * BB * HH];  // layer-1 h, TRANSPOSED [t][k][b]
__device__ int   g_flag0[SEQ];
__device__ int   g_flag1[SEQ];

// ---------------------------------------------------------------- helpers
__device__ __forceinline__ int ld_acq(const int* p) {
    int v;
    asm volatile("ld.acquire.gpu.s32 %0, [%1];" : "=r"(v) : "l"(p) : "memory");
    return v;
}
__device__ __forceinline__ void red_release(int* p) {
    asm volatile("red.release.gpu.global.add.s32 [%0], 1;" :: "l"(p) : "memory");
}
__device__ __forceinline__ u64 dup2(float x) {
    u64 r;
    asm("mov.b64 %0, {%1, %1};" : "=l"(r) : "f"(x));
    return r;
}
__device__ __forceinline__ u64 pk2(float a, float b) {
    u64 r;
    asm("mov.b64 %0, {%1, %2};" : "=l"(r) : "f"(a), "f"(b));
    return r;
}
__device__ __forceinline__ void fma2(u64& acc, u64 a, u64 b) {
    asm("fma.rn.f32x2 %0, %1, %2, %0;" : "+l"(acc) : "l"(a), "l"(b));
}
__device__ __forceinline__ u64 add2(u64 a, u64 b) {
    u64 r;
    asm("add.rn.f32x2 %0, %1, %2;" : "=l"(r) : "l"(a), "l"(b));
    return r;
}
__device__ __forceinline__ float2 unp2(u64 v) {
    float2 f;
    asm("mov.b64 {%0, %1}, %2;" : "=f"(f.x), "=f"(f.y) : "l"(v));
    return f;
}
__device__ __forceinline__ void cp16(uint32_t s, const void* g) {
    asm volatile("cp.async.cg.shared.global [%0], [%1], 16;" :: "r"(s), "l"(g));
}
__device__ __forceinline__ void cp_commit() {
    asm volatile("cp.async.commit_group;" ::: "memory");
}
#define CP_WAIT(N) asm volatile("cp.async.wait_group %0;" :: "n"(N) : "memory")
#define BARH(id)   asm volatile("bar.sync %0, 128;" :: "r"(id) : "memory")

// Copy one 32KB chunk (128 transposed k-rows x 64 floats, contiguous) into hs.
// Done by the 128 threads of one K-half. baseF in floats.
__device__ __forceinline__ void stage_chunk(uint32_t s0, const float* src,
                                            int baseF, int lane) {
    const float* g = src + baseF;
    uint32_t d = s0 + (uint32_t)baseF * 4u;
#pragma unroll
    for (int j = 0; j < 16; j++) {
        int i = lane + j * 128;          // 0..2047 16B units
        cp16(d + (uint32_t)i * 16u, g + (size_t)i * 4);
    }
    cp_commit();
}

// ---------------------------------------------------------------------------
// Transpose h_init (L,B,H b-major) into g_h0T/g_h1T slot 0 ([k][b]).
// ---------------------------------------------------------------------------
__global__ void transpose_hinit(const float* __restrict__ h) {
    int i = blockIdx.x * 256 + threadIdx.x;   // 0..32767
    int k = i >> 6, b = i & 63;
    g_h0T[i] = h[(size_t)b * HH + k];
    g_h1T[i] = h[(size_t)BB * HH + (size_t)b * HH + k];
}

// ---------------------------------------------------------------------------
// Precompute Z0 = X @ Wx0 + bx0 + bh0 (packed fp32 inner) + zero the flags.
// ---------------------------------------------------------------------------
__global__ __launch_bounds__(256) void precompute_z0(
    const float* __restrict__ X,
    const float* __restrict__ W,
    const float* __restrict__ bxv,
    const float* __restrict__ bhv)
{
    __shared__ float As[16][64];
    __shared__ float Bs[16][64];
    const int tid = threadIdx.x;

    if (blockIdx.y == 0 && blockIdx.x < 4) {
        int i = blockIdx.x * 256 + tid;
        g_flag0[i] = 0;
        g_flag1[i] = 0;
    }

    const int tx = tid & 15;
    const int ty = tid >> 4;
    const int m0 = blockIdx.x * 64;
    const int n0 = blockIdx.y * 64;
    const int lm = tid >> 2;
    const int lk = (tid & 3) << 2;
    const int lr = tid >> 4;
    const int lc = (tid & 15) << 2;

    u64 acc[4][2];
#pragma unroll
    for (int i = 0; i < 4; i++) { acc[i][0] = 0ULL; acc[i][1] = 0ULL; }

    for (int kc = 0; kc < DD; kc += 16) {
        float4 a4 = *(const float4*)(X + (size_t)(m0 + lm) * DD + kc + lk);
        float4 b4 = *(const float4*)(W + (size_t)(kc + lr) * HH + n0 + lc);
        As[lk + 0][lm] = a4.x;
        As[lk + 1][lm] = a4.y;
        As[lk + 2][lm] = a4.z;
        As[lk + 3][lm] = a4.w;
        *(float4*)&Bs[lr][lc] = b4;
        __syncthreads();
#pragma unroll
        for (int kk = 0; kk < 16; kk++) {
            float4 av = *(const float4*)&As[kk][ty << 2];
            ulonglong2 bq = *(const ulonglong2*)&Bs[kk][tx << 2];
            u64 d;
            d = dup2(av.x); fma2(acc[0][0], d, bq.x); fma2(acc[0][1], d, bq.y);
            d = dup2(av.y); fma2(acc[1][0], d, bq.x); fma2(acc[1][1], d, bq.y);
            d = dup2(av.z); fma2(acc[2][0], d, bq.x); fma2(acc[2][1], d, bq.y);
            d = dup2(av.w); fma2(acc[3][0], d, bq.x); fma2(acc[3][1], d, bq.y);
        }
        __syncthreads();
    }
    const int n = n0 + (tx << 2);
    float4 bx4 = *(const float4*)(bxv + n);
    float4 bh4 = *(const float4*)(bhv + n);
#pragma unroll
    for (int i = 0; i < 4; i++) {
        int m = m0 + (ty << 2) + i;
        float2 c0 = unp2(acc[i][0]);
        float2 c1 = unp2(acc[i][1]);
        float4 o;
        o.x = c0.x + bx4.x + bh4.x;
        o.y = c0.y + bx4.y + bh4.y;
        o.z = c1.x + bx4.z + bh4.z;
        o.w = c1.y + bx4.w + bh4.w;
        *(float4*)(g_z0 + (size_t)m * HH + n) = o;
    }
}

// ---------------------------------------------------------------------------
// Persistent sequential kernel. 96 CTAs (1/SM), 256 threads.
// Thread map (both layers): bp = tid&31 (batch pair), cp = (tid>>5)&3,
// kh = tid>>7 (K half). Inner loop: h packed (b0,b1) via LDS.64 from
// transposed hs; weights pre-duplicated (w,w) u64 in SMEM. No movs.
// ---------------------------------------------------------------------------
__global__ __launch_bounds__(256) void rnn_seq(
    const float* __restrict__ Wh0,
    const float* __restrict__ Wx1,
    const float* __restrict__ bx1,
    const float* __restrict__ Wh1,
    const float* __restrict__ bh1,
    float* __restrict__ out)
{
    extern __shared__ float sm[];
    float* hs = sm;                        // 32768 floats: hs[k][b] (64 f/row)
    u64*  wd  = (u64*)(sm + 32768);        // 8192 u64 dup weights
    u64*  red = wd + 8192;                 // 512 u64 reduction
    const int tid  = threadIdx.x;
    const int bp   = tid & 31;
    const int cp   = (tid >> 5) & 3;
    const int kh   = tid >> 7;
    const int lane = tid & 127;
    const int kbase = kh << 8;             // 0 / 256
    const uint32_t s0 = (uint32_t)__cvta_generic_to_shared(hs);
    const float* hsbp = hs + 2 * bp;

    if (blockIdx.x < NCTA0) {
        // ------------------------- layer 0: 16 cols -------------------------
        const int n0 = blockIdx.x * 16;
        for (int i = tid; i < 512 * 16; i += 256) {
            int k = i >> 4, c = i & 15;
            wd[i] = dup2(Wh0[(size_t)k * HH + n0 + c]);
        }
        const u64* wq = wd + cp * 4;       // 4 cols per thread
        __syncthreads();

        for (int t = 0; t < SEQ; t++) {
            if (tid == 0 && t > 0) {
                while (ld_acq(&g_flag0[t - 1]) < NCTA0) {}
            }
            __syncthreads();
            const float* srcT = g_h0T + (size_t)t * BB * HH;
            stage_chunk(s0, srcT, kh * 16384,        lane);
            stage_chunk(s0, srcT, kh * 16384 + 8192, lane);

            const float* zp = g_z0 + (size_t)t * BB * HH
                              + (size_t)(2 * bp) * HH + n0 + cp * 4;
            float4 zr0 = *(const float4*)zp;
            float4 zr1 = *(const float4*)(zp + HH);

            u64 a0 = 0, a1 = 0, a2 = 0, a3 = 0;
#pragma unroll
            for (int half = 0; half < 2; half++) {
                if (half == 0) { CP_WAIT(1); } else { CP_WAIT(0); }
                BARH(1 + kh);
                const int ks = kbase + half * 128;
#pragma unroll 8
                for (int k = ks; k < ks + 128; k += 2) {
                    u64 hA = *(const u64*)(hsbp + (size_t)k * 64);
                    u64 hB = *(const u64*)(hsbp + (size_t)(k + 1) * 64);
                    ulonglong2 wA0 = *(const ulonglong2*)(wq + (size_t)k * 16);
                    ulonglong2 wA1 = *(const ulonglong2*)(wq + (size_t)k * 16 + 2);
                    ulonglong2 wB0 = *(const ulonglong2*)(wq + (size_t)(k + 1) * 16);
                    ulonglong2 wB1 = *(const ulonglong2*)(wq + (size_t)(k + 1) * 16 + 2);
                    fma2(a0, hA, wA0.x); fma2(a1, hA, wA0.y);
                    fma2(a2, hA, wA1.x); fma2(a3, hA, wA1.y);
                    fma2(a0, hB, wB0.x); fma2(a1, hB, wB0.y);
                    fma2(a2, hB, wB1.x); fma2(a3, hB, wB1.y);
                }
            }

            if (kh) {
                u64* r = red + (size_t)lane * 4;
                r[0] = a0; r[1] = a1; r[2] = a2; r[3] = a3;
            }
            __syncthreads();
            if (!kh) {
                const u64* r = red + (size_t)lane * 4;
                a0 = add2(a0, r[0]); a1 = add2(a1, r[1]);
                a2 = add2(a2, r[2]); a3 = add2(a3, r[3]);
                float2 p0 = unp2(a0), p1 = unp2(a1), p2 = unp2(a2), p3 = unp2(a3);
                float v00 = tanhf(p0.x + zr0.x), v10 = tanhf(p0.y + zr1.x);
                float v01 = tanhf(p1.x + zr0.y), v11 = tanhf(p1.y + zr1.y);
                float v02 = tanhf(p2.x + zr0.z), v12 = tanhf(p2.y + zr1.z);
                float v03 = tanhf(p3.x + zr0.w), v13 = tanhf(p3.y + zr1.w);
                float* gT = g_h0T + (size_t)(t + 1) * BB * HH
                            + (size_t)(n0 + cp * 4) * 64 + 2 * bp;
                *(u64*)(gT)       = pk2(v00, v10);
                *(u64*)(gT + 64)  = pk2(v01, v11);
                *(u64*)(gT + 128) = pk2(v02, v12);
                *(u64*)(gT + 192) = pk2(v03, v13);
                if (t == SEQ - 1) {
                    float* hn = out + (size_t)SEQ * BB * HH
                                + (size_t)(2 * bp) * HH + n0 + cp * 4;
                    *(float4*)hn        = make_float4(v00, v01, v02, v03);
                    *(float4*)(hn + HH) = make_float4(v10, v11, v12, v13);
                }
            }
            __syncthreads();
            if (tid == 0) red_release(&g_flag0[t]);
        }
    } else {
        // ------------------------- layer 1: 8 cols -------------------------
        const int n0 = (blockIdx.x - NCTA0) * 8;
        u64* wdA = wd;           // Wh1 dup [512][8]
        u64* wdB = wd + 4096;    // Wx1 dup [512][8]
        for (int i = tid; i < 512 * 8; i += 256) {
            int k = i >> 3, c = i & 7;
            wdA[i] = dup2(Wh1[(size_t)k * HH + n0 + c]);
            wdB[i] = dup2(Wx1[(size_t)k * HH + n0 + c]);
        }
        const int nn = n0 + cp * 2;
        const u64* wA2 = wdA + cp * 2;
        const u64* wB2 = wdB + cp * 2;
        const float bias0 = bx1[nn] + bh1[nn];
        const float bias1 = bx1[nn + 1] + bh1[nn + 1];
        __syncthreads();

        for (int t = 0; t < SEQ; t++) {
            if (tid == 0 && t > 0) {
                while (ld_acq(&g_flag1[t - 1]) < NCTA1) {}
            }
            __syncthreads();

            u64 c0 = 0, c1 = 0;
            // phase A: h1[t-1] @ Wh1 (data ready at step start)
            {
                const float* srcA = g_h1T + (size_t)t * BB * HH;
                stage_chunk(s0, srcA, kh * 16384,        lane);
                stage_chunk(s0, srcA, kh * 16384 + 8192, lane);
#pragma unroll
                for (int half = 0; half < 2; half++) {
                    if (half == 0) { CP_WAIT(1); } else { CP_WAIT(0); }
                    BARH(1 + kh);
                    const int ks = kbase + half * 128;
#pragma unroll 8
                    for (int k = ks; k < ks + 128; k += 2) {
                        u64 hA = *(const u64*)(hsbp + (size_t)k * 64);
                        u64 hB = *(const u64*)(hsbp + (size_t)(k + 1) * 64);
                        ulonglong2 wA = *(const ulonglong2*)(wA2 + (size_t)k * 8);
                        ulonglong2 wB = *(const ulonglong2*)(wA2 + (size_t)(k + 1) * 8);
                        fma2(c0, hA, wA.x); fma2(c1, hA, wA.y);
                        fma2(c0, hB, wB.x); fma2(c1, hB, wB.y);
                    }
                }
            }
            // phase B: h0[t] @ Wx1 (critical tail)
            if (tid == 0) {
                while (ld_acq(&g_flag0[t]) < NCTA0) {}
            }
            __syncthreads();   // all done reading hs(h1); acquire published
            {
                const float* srcB = g_h0T + (size_t)(t + 1) * BB * HH;
                stage_chunk(s0, srcB, kh * 16384,        lane);
                stage_chunk(s0, srcB, kh * 16384 + 8192, lane);
#pragma unroll
                for (int half = 0; half < 2; half++) {
                    if (half == 0) { CP_WAIT(1); } else { CP_WAIT(0); }
                    BARH(1 + kh);
                    const int ks = kbase + half * 128;
#pragma unroll 8
                    for (int k = ks; k < ks + 128; k += 2) {
                        u64 hA = *(const u64*)(hsbp + (size_t)k * 64);
                        u64 hB = *(const u64*)(hsbp + (size_t)(k + 1) * 64);
                        ulonglong2 wA = *(const ulonglong2*)(wB2 + (size_t)k * 8);
                        ulonglong2 wB = *(const ulonglong2*)(wB2 + (size_t)(k + 1) * 8);
                        fma2(c0, hA, wA.x); fma2(c1, hA, wA.y);
                        fma2(c0, hB, wB.x); fma2(c1, hB, wB.y);
                    }
                }
            }

            if (kh) {
                u64* r = red + (size_t)lane * 2;
                r[0] = c0; r[1] = c1;
            }
            __syncthreads();
            if (!kh) {
                const u64* r = red + (size_t)lane * 2;
                c0 = add2(c0, r[0]); c1 = add2(c1, r[1]);
                float2 pa = unp2(c0), pb = unp2(c1);
                float v00 = tanhf(pa.x + bias0), v10 = tanhf(pa.y + bias0);
                float v01 = tanhf(pb.x + bias1), v11 = tanhf(pb.y + bias1);
                float* o = out + (size_t)t * BB * HH
                           + (size_t)(2 * bp) * HH + nn;
                *(float2*)o        = make_float2(v00, v01);
                *(float2*)(o + HH) = make_float2(v10, v11);
                float* gT = g_h1T + (size_t)(t + 1) * BB * HH
                            + (size_t)nn * 64 + 2 * bp;
                *(u64*)gT        = pk2(v00, v10);
                *(u64*)(gT + 64) = pk2(v01, v11);
                if (t == SEQ - 1) {
                    float* hn = out + (size_t)SEQ * BB * HH + BB * HH
                                + (size_t)(2 * bp) * HH + nn;
                    *(float2*)hn        = make_float2(v00, v01);
                    *(float2*)(hn + HH) = make_float2(v10, v11);
                }
            }
            __syncthreads();
            if (tid == 0) red_release(&g_flag1[t]);
        }
    }
}

#define SMEM_BYTES (131072 + 65536 + 4096)

extern "C" void kernel_launch(void* const* d_in, const int* in_sizes, int n_in,
                              void* d_out, int out_size)
{
    const float* x   = (const float*)d_in[0];
    const float* h0  = (const float*)d_in[1];
    const float* Wx0 = (const float*)d_in[2];
    const float* bx0 = (const float*)d_in[3];
    const float* Wh0 = (const float*)d_in[4];
    const float* bh0 = (const float*)d_in[5];
    const float* Wx1 = (const float*)d_in[6];
    const float* bx1 = (const float*)d_in[7];
    const float* Wh1 = (const float*)d_in[8];
    const float* bh1 = (const float*)d_in[9];
    float* out = (float*)d_out;
    (void)in_sizes; (void)n_in; (void)out_size;

    transpose_hinit<<<128, 256>>>(h0);

    dim3 gz((SEQ * BB) / 64, HH / 64);
    precompute_z0<<<gz, 256>>>(x, Wx0, bx0, bh0);

    static int attr_set = 0;
    if (!attr_set) {
        cudaFuncSetAttribute(rnn_seq, cudaFuncAttributeMaxDynamicSharedMemorySize,
                             SMEM_BYTES);
        attr_set = 1;
    }
    rnn_seq<<<NCTA0 + NCTA1, 256, SMEM_BYTES>>>(Wh0, Wx1, bx1, Wh1, bh1, out);
}

// round 7
// speedup vs baseline: 1.2105x; 1.1159x over previous
#include <cuda_runtime.h>
#include <math.h>
#include <stdint.h>

#define SEQ 1024
#define BB  64
#define DD  512
#define HH  512
#define BH  (BB * HH)

#define NCTA0 64   // layer-0 CTAs, 8 cols each
#define NCTA1 64   // layer-1 CTAs, 8 cols each
#define NTHR  128

typedef unsigned long long u64;

// Scratch (allocation-free rule: __device__ globals)
__device__ float g_z0[SEQ * BB * HH];   // x@Wx0 + bx0 + bh0 (b-major)
__device__ float g_h0[SEQ * BB * HH];   // layer-0 hidden history (b-major)
__device__ int   g_flag0[SEQ];
__device__ int   g_flag1[SEQ];

// ---------------------------------------------------------------- helpers
__device__ __forceinline__ int ld_acq(const int* p) {
    int v;
    asm volatile("ld.acquire.gpu.s32 %0, [%1];" : "=r"(v) : "l"(p) : "memory");
    return v;
}
__device__ __forceinline__ void red_release(int* p) {
    asm volatile("red.release.gpu.global.add.s32 [%0], 1;" :: "l"(p) : "memory");
}
__device__ __forceinline__ void wait_flag(const int* p, int target) {
    while (ld_acq(p) < target) {}
}
__device__ __forceinline__ u64 dup2(float x) {
    u64 r; asm("mov.b64 %0, {%1, %1};" : "=l"(r) : "f"(x)); return r;
}
__device__ __forceinline__ void fma2(u64& acc, u64 a, u64 b) {
    asm("fma.rn.f32x2 %0, %1, %2, %0;" : "+l"(acc) : "l"(a), "l"(b));
}
__device__ __forceinline__ u64 add2(u64 a, u64 b) {
    u64 r; asm("add.rn.f32x2 %0, %1, %2;" : "=l"(r) : "l"(a), "l"(b)); return r;
}
__device__ __forceinline__ float2 unp2(u64 v) {
    float2 f; asm("mov.b64 {%0, %1}, %2;" : "=f"(f.x), "=f"(f.y) : "l"(v)); return f;
}
__device__ __forceinline__ void cp16(uint32_t s, const void* g) {
    asm volatile("cp.async.cg.shared.global [%0], [%1], 16;" :: "r"(s), "l"(g));
}
__device__ __forceinline__ void cp_commit() {
    asm volatile("cp.async.commit_group;" ::: "memory");
}
#define CP_WAIT(N) asm volatile("cp.async.wait_group %0;" :: "n"(N) : "memory")

#define HS0 516   // L0 full h row stride (floats): 2064B ≡ 16 (mod 128) — conflict-free
#define HS1 260   // L1 half-buffer row stride:     1040B ≡ 16 (mod 128)
#define WS0 516   // L0 wT row stride
#define WS1 1032  // L1 wT row stride (K=1024)

// Stage one 256-k half of h (64 rows x 256 floats = 64KB) into L0's full hs.
// 32 cp16/thread: id 0..4095 -> b = id>>6 (row), kc = id&63 (16B unit).
__device__ __forceinline__ void stageL0(uint32_t s0, const float* src, int half, int tid) {
#pragma unroll
    for (int j = 0; j < 32; j++) {
        int id = tid + j * NTHR;            // 0..4095
        int b = id >> 6, kc = id & 63;
        cp16(s0 + (uint32_t)((b * HS0 + half * 256 + kc * 4) * 4),
             src + (size_t)b * HH + half * 256 + kc * 4);
    }
    cp_commit();
}

// Stage 256 k's (koff..koff+255) of h (64KB) into an L1 half-buffer. 32 cp16/thread.
__device__ __forceinline__ void stage260(uint32_t sbuf, const float* src, int koff, int tid) {
#pragma unroll
    for (int j = 0; j < 32; j++) {
        int id = tid + j * NTHR;            // 0..4095
        int b = id >> 6, kc = id & 63;
        cp16(sbuf + (uint32_t)((b * HS1 + kc * 4) * 4),
             src + (size_t)b * HH + koff + kc * 4);
    }
    cp_commit();
}

// 32-k segment of the GEMV. 4 batches x 8 cols per thread, K-packed f32x2.
// h rows hr[m] point at (hs + (bg+16m)*stride + klocal); wk points at wT + kcol.
// acc[m*8+c] holds (sum_even, sum_odd).
template<int WS>
__device__ __forceinline__ void seg32(u64* acc,
                                      const float* hr0, const float* hr1,
                                      const float* hr2, const float* hr3,
                                      const float* wk)
{
#pragma unroll 4
    for (int i = 0; i < 32; i += 4) {
        ulonglong2 ha = *(const ulonglong2*)(hr0 + i);
        ulonglong2 hb = *(const ulonglong2*)(hr1 + i);
        ulonglong2 hc = *(const ulonglong2*)(hr2 + i);
        ulonglong2 hd = *(const ulonglong2*)(hr3 + i);
#pragma unroll
        for (int c = 0; c < 8; c++) {
            ulonglong2 w = *(const ulonglong2*)(wk + c * WS + i);
            fma2(acc[c],      ha.x, w.x);  fma2(acc[c],      ha.y, w.y);
            fma2(acc[8 + c],  hb.x, w.x);  fma2(acc[8 + c],  hb.y, w.y);
            fma2(acc[16 + c], hc.x, w.x);  fma2(acc[16 + c], hc.y, w.y);
            fma2(acc[24 + c], hd.x, w.x);  fma2(acc[24 + c], hd.y, w.y);
        }
    }
}

// Write this thread's 32 partials to red[ks][bg][32] (contiguous 256B).
__device__ __forceinline__ void store_partials(u64* red, const u64* acc, int tid) {
    u64* wr = red + (size_t)(tid >> 4) * 512 + (size_t)(tid & 15) * 32;
#pragma unroll
    for (int j = 0; j < 16; j++)
        *(ulonglong2*)(wr + 2 * j) = make_ulonglong2(acc[2 * j], acc[2 * j + 1]);
}

// Reduce 8 k-slices for this thread's 4 outputs (b = tid&63, cols ch*4..ch*4+3).
__device__ __forceinline__ float4 reduce_outputs(const u64* red, int b, int ch) {
    const u64* rp = red + (size_t)(b & 15) * 32 + (size_t)(b >> 4) * 8 + ch * 4;
    u64 s0 = 0, s1 = 0, s2 = 0, s3 = 0;
#pragma unroll
    for (int ks = 0; ks < 8; ks++) {
        ulonglong2 p0 = *(const ulonglong2*)(rp + (size_t)ks * 512);
        ulonglong2 p1 = *(const ulonglong2*)(rp + (size_t)ks * 512 + 2);
        s0 = add2(s0, p0.x); s1 = add2(s1, p0.y);
        s2 = add2(s2, p1.x); s3 = add2(s3, p1.y);
    }
    float2 f0 = unp2(s0), f1 = unp2(s1), f2 = unp2(s2), f3 = unp2(s3);
    return make_float4(f0.x + f0.y, f1.x + f1.y, f2.x + f2.y, f3.x + f3.y);
}

// ---------------------------------------------------------------------------
// Precompute Z0 = X @ Wx0 + bx0 + bh0 + zero the flags.
// ---------------------------------------------------------------------------
__global__ __launch_bounds__(256) void precompute_z0(
    const float* __restrict__ X,
    const float* __restrict__ W,
    const float* __restrict__ bxv,
    const float* __restrict__ bhv)
{
    __shared__ float As[16][64];
    __shared__ float Bs[16][64];
    const int tid = threadIdx.x;

    if (blockIdx.y == 0 && blockIdx.x < 4) {
        int i = blockIdx.x * 256 + tid;
        g_flag0[i] = 0;
        g_flag1[i] = 0;
    }

    const int tx = tid & 15;
    const int ty = tid >> 4;
    const int m0 = blockIdx.x * 64;
    const int n0 = blockIdx.y * 64;
    const int lm = tid >> 2;
    const int lk = (tid & 3) << 2;
    const int lr = tid >> 4;
    const int lc = (tid & 15) << 2;

    u64 acc[4][2];
#pragma unroll
    for (int i = 0; i < 4; i++) { acc[i][0] = 0ULL; acc[i][1] = 0ULL; }

    for (int kc = 0; kc < DD; kc += 16) {
        float4 a4 = *(const float4*)(X + (size_t)(m0 + lm) * DD + kc + lk);
        float4 b4 = *(const float4*)(W + (size_t)(kc + lr) * HH + n0 + lc);
        As[lk + 0][lm] = a4.x;
        As[lk + 1][lm] = a4.y;
        As[lk + 2][lm] = a4.z;
        As[lk + 3][lm] = a4.w;
        *(float4*)&Bs[lr][lc] = b4;
        __syncthreads();
#pragma unroll
        for (int kk = 0; kk < 16; kk++) {
            float4 av = *(const float4*)&As[kk][ty << 2];
            ulonglong2 bq = *(const ulonglong2*)&Bs[kk][tx << 2];
            u64 d;
            d = dup2(av.x); fma2(acc[0][0], d, bq.x); fma2(acc[0][1], d, bq.y);
            d = dup2(av.y); fma2(acc[1][0], d, bq.x); fma2(acc[1][1], d, bq.y);
            d = dup2(av.z); fma2(acc[2][0], d, bq.x); fma2(acc[2][1], d, bq.y);
            d = dup2(av.w); fma2(acc[3][0], d, bq.x); fma2(acc[3][1], d, bq.y);
        }
        __syncthreads();
    }
    const int n = n0 + (tx << 2);
    float4 bx4 = *(const float4*)(bxv + n);
    float4 bh4 = *(const float4*)(bhv + n);
#pragma unroll
    for (int i = 0; i < 4; i++) {
        int m = m0 + (ty << 2) + i;
        float2 c0 = unp2(acc[i][0]);
        float2 c1 = unp2(acc[i][1]);
        float4 o;
        o.x = c0.x + bx4.x + bh4.x;
        o.y = c0.y + bx4.y + bh4.y;
        o.z = c1.x + bx4.z + bh4.z;
        o.w = c1.y + bx4.w + bh4.w;
        *(float4*)(g_z0 + (size_t)m * HH + n) = o;
    }
}

// ---------------------------------------------------------------------------
// Persistent sequential kernel. 128 CTAs (1/SM), 128 threads.
//   blocks [0,64):   layer 0, 8 cols, K=512      (SMEM-BW-bound ~3K cyc/step)
//   blocks [64,128): layer 1, 8 cols, K=1024 concat [h1[t-1]; h0[t]]
// Thread tile: 4 batches (stride 16) x 8 cols, K-packed f32x2, 8 k-slices,
// 32KB SMEM reduction. cp.async half-buffers overlap staging with compute.
// ---------------------------------------------------------------------------
__global__ __launch_bounds__(NTHR) void rnn_seq(
    const float* __restrict__ h_init,
    const float* __restrict__ Wh0,
    const float* __restrict__ Wx1,
    const float* __restrict__ bx1,
    const float* __restrict__ Wh1,
    const float* __restrict__ bh1,
    float* __restrict__ out)
{
    extern __shared__ float sm[];
    const int tid = threadIdx.x;
    const int bg  = tid & 15;     // batch group (low bits → conflict-free lanes)
    const int ks  = tid >> 4;     // k-slice 0..7
    const int ob  = tid & 63;     // output batch (reducer role)
    const int och = tid >> 6;     // output col half (0/1)

    if (blockIdx.x < NCTA0) {
        // ------------------------- layer 0 -------------------------
        const int n0 = blockIdx.x * 8;
        float* hs  = sm;                      // [64][HS0]
        float* wsT = sm + 64 * HS0;           // [8][WS0]
        u64*   red = (u64*)sm;                // aliases hs after compute
        const uint32_t s0 = (uint32_t)__cvta_generic_to_shared(hs);

        for (int i = tid; i < 1024; i += NTHR) {
            int k = i >> 1, cq = i & 1;
            float4 v = *(const float4*)(Wh0 + (size_t)k * HH + n0 + cq * 4);
            wsT[(cq * 4 + 0) * WS0 + k] = v.x;
            wsT[(cq * 4 + 1) * WS0 + k] = v.y;
            wsT[(cq * 4 + 2) * WS0 + k] = v.z;
            wsT[(cq * 4 + 3) * WS0 + k] = v.w;
        }
        __syncthreads();

        const float* hr0 = hs + (bg +  0) * HS0;
        const float* hr1 = hs + (bg + 16) * HS0;
        const float* hr2 = hs + (bg + 32) * HS0;
        const float* hr3 = hs + (bg + 48) * HS0;
        const int ko = ks * 32;

        for (int t = 0; t < SEQ; t++) {
            // z prefetch (no dependence on flags)
            const float* zp = g_z0 + (size_t)t * BH + (size_t)ob * HH + n0 + och * 4;
            float4 zv = *(const float4*)zp;

            if (t > 0) wait_flag(&g_flag0[t - 1], NCTA0);
            const float* hp = (t == 0) ? h_init : (g_h0 + (size_t)(t - 1) * BH);
            stageL0(s0, hp, 0, tid);
            stageL0(s0, hp, 1, tid);

            u64 acc[32];
#pragma unroll
            for (int i = 0; i < 32; i++) acc[i] = 0ULL;

            CP_WAIT(1); __syncthreads();
            seg32<WS0>(acc, hr0 + ko, hr1 + ko, hr2 + ko, hr3 + ko, wsT + ko);
            CP_WAIT(0); __syncthreads();
            seg32<WS0>(acc, hr0 + 256 + ko, hr1 + 256 + ko, hr2 + 256 + ko,
                       hr3 + 256 + ko, wsT + 256 + ko);
            __syncthreads();                 // everyone done with hs
            store_partials(red, acc, tid);
            __syncthreads();
            float4 r = reduce_outputs(red, ob, och);
            float4 v;
            v.x = tanhf(r.x + zv.x); v.y = tanhf(r.y + zv.y);
            v.z = tanhf(r.z + zv.z); v.w = tanhf(r.w + zv.w);
            *(float4*)(g_h0 + (size_t)t * BH + (size_t)ob * HH + n0 + och * 4) = v;
            if (t == SEQ - 1)
                *(float4*)(out + (size_t)SEQ * BH + (size_t)ob * HH + n0 + och * 4) = v;
            __syncthreads();
            if (tid == 0) red_release(&g_flag0[t]);
        }
    } else {
        // ------------------------- layer 1 -------------------------
        const int n0 = (blockIdx.x - NCTA0) * 8;
        float* buf0 = sm;                     // [64][HS1]
        float* buf1 = sm + 64 * HS1;          // [64][HS1]
        float* wsT  = sm + 2 * 64 * HS1;      // [8][WS1]: cols 0..511 Wh1, 512..1023 Wx1
        u64*   red  = (u64*)sm;               // aliases buf0 after compute
        const uint32_t sb0 = (uint32_t)__cvta_generic_to_shared(buf0);
        const uint32_t sb1 = (uint32_t)__cvta_generic_to_shared(buf1);

        for (int i = tid; i < 1024; i += NTHR) {
            int k = i >> 1, cq = i & 1;
            float4 vh = *(const float4*)(Wh1 + (size_t)k * HH + n0 + cq * 4);
            float4 vx = *(const float4*)(Wx1 + (size_t)k * HH + n0 + cq * 4);
            wsT[(cq * 4 + 0) * WS1 + k] = vh.x;
            wsT[(cq * 4 + 1) * WS1 + k] = vh.y;
            wsT[(cq * 4 + 2) * WS1 + k] = vh.z;
            wsT[(cq * 4 + 3) * WS1 + k] = vh.w;
            wsT[(cq * 4 + 0) * WS1 + 512 + k] = vx.x;
            wsT[(cq * 4 + 1) * WS1 + 512 + k] = vx.y;
            wsT[(cq * 4 + 2) * WS1 + 512 + k] = vx.z;
            wsT[(cq * 4 + 3) * WS1 + 512 + k] = vx.w;
        }
        float4 bias;
        {
            const float* bx = bx1 + n0 + och * 4;
            const float* bh = bh1 + n0 + och * 4;
            bias.x = bx[0] + bh[0]; bias.y = bx[1] + bh[1];
            bias.z = bx[2] + bh[2]; bias.w = bx[3] + bh[3];
        }
        __syncthreads();

        const int bo0 = (bg +  0) * HS1, bo1 = (bg + 16) * HS1;
        const int bo2 = (bg + 32) * HS1, bo3 = (bg + 48) * HS1;
        const int ko = ks * 32;

        for (int t = 0; t < SEQ; t++) {
            if (t > 0) wait_flag(&g_flag1[t - 1], NCTA1);
            const float* h1src = (t == 0) ? (h_init + BH) : (out + (size_t)(t - 1) * BH);

            stage260(sb0, h1src, 0, tid);     // A0
            stage260(sb1, h1src, 256, tid);   // A1

            u64 acc[32];
#pragma unroll
            for (int i = 0; i < 32; i++) acc[i] = 0ULL;

            // seg a0: h1 k 0..255 (buf0), wT cols 0..255
            CP_WAIT(1); __syncthreads();
            seg32<WS1>(acc, buf0 + bo0 + ko, buf0 + bo1 + ko, buf0 + bo2 + ko,
                       buf0 + bo3 + ko, wsT + ko);
            CP_WAIT(0); __syncthreads();      // buf1 ready, buf0 consumed

            // kick off B0 staging (h0[t]) while computing a1
            wait_flag(&g_flag0[t], NCTA0);
            const float* h0src = g_h0 + (size_t)t * BH;
            stage260(sb0, h0src, 0, tid);     // B0

            // seg a1: h1 k 256..511 (buf1), wT cols 256..511
            seg32<WS1>(acc, buf1 + bo0 + ko, buf1 + bo1 + ko, buf1 + bo2 + ko,
                       buf1 + bo3 + ko, wsT + 256 + ko);
            CP_WAIT(0); __syncthreads();      // B0 ready, buf1 consumed

            stage260(sb1, h0src, 256, tid);   // B1

            // seg b0: h0 k 0..255 (buf0), wT cols 512..767
            seg32<WS1>(acc, buf0 + bo0 + ko, buf0 + bo1 + ko, buf0 + bo2 + ko,
                       buf0 + bo3 + ko, wsT + 512 + ko);
            CP_WAIT(0); __syncthreads();      // B1 ready, buf0 consumed

            // seg b1: h0 k 256..511 (buf1), wT cols 768..1023
            seg32<WS1>(acc, buf1 + bo0 + ko, buf1 + bo1 + ko, buf1 + bo2 + ko,
                       buf1 + bo3 + ko, wsT + 768 + ko);
            __syncthreads();                  // buf1 consumed (red aliases buf0)

            store_partials(red, acc, tid);
            __syncthreads();
            float4 r = reduce_outputs(red, ob, och);
            float4 v;
            v.x = tanhf(r.x + bias.x); v.y = tanhf(r.y + bias.y);
            v.z = tanhf(r.z + bias.z); v.w = tanhf(r.w + bias.w);
            *(float4*)(out + (size_t)t * BH + (size_t)ob * HH + n0 + och * 4) = v;
            if (t == SEQ - 1)
                *(float4*)(out + (size_t)SEQ * BH + BH + (size_t)ob * HH + n0 + och * 4) = v;
            __syncthreads();
            if (tid == 0) red_release(&g_flag1[t]);
        }
    }
}

// L1 smem: 2*64*260*4 + 8*1032*4 = 133120 + 33024 = 166144 (L0 needs 148608)
#define SMEM_BYTES 166144

extern "C" void kernel_launch(void* const* d_in, const int* in_sizes, int n_in,
                              void* d_out, int out_size)
{
    const float* x   = (const float*)d_in[0];
    const float* h0  = (const float*)d_in[1];
    const float* Wx0 = (const float*)d_in[2];
    const float* bx0 = (const float*)d_in[3];
    const float* Wh0 = (const float*)d_in[4];
    const float* bh0 = (const float*)d_in[5];
    const float* Wx1 = (const float*)d_in[6];
    const float* bx1 = (const float*)d_in[7];
    const float* Wh1 = (const float*)d_in[8];
    const float* bh1 = (const float*)d_in[9];
    float* out = (float*)d_out;
    (void)in_sizes; (void)n_in; (void)out_size;

    dim3 gz((SEQ * BB) / 64, HH / 64);
    precompute_z0<<<gz, 256>>>(x, Wx0, bx0, bh0);

    static int attr_set = 0;
    if (!attr_set) {
        cudaFuncSetAttribute(rnn_seq, cudaFuncAttributeMaxDynamicSharedMemorySize,
                             SMEM_BYTES);
        attr_set = 1;
    }
    rnn_seq<<<NCTA0 + NCTA1, NTHR, SMEM_BYTES>>>(h0, Wh0, Wx1, bx1, Wh1, bh1, out);
}

// round 8
// speedup vs baseline: 1.5396x; 1.2719x over previous
#include <cuda_runtime.h>
#include <math.h>
#include <stdint.h>

#define SEQ 1024
#define BB  64
#define DD  512
#define HH  512
#define BH  (BB * HH)

#define NCTA0 64   // layer-0 CTAs, 8 cols each
#define NCTA1 64   // layer-1 CTAs, 8 cols each
#define NTHR  256

typedef unsigned long long u64;

// Scratch (allocation-free rule: __device__ globals)
__device__ float g_z0[SEQ * BB * HH];   // x@Wx0 + bx0 + bh0 (b-major)
__device__ float g_h0[SEQ * BB * HH];   // layer-0 hidden history (b-major)
__device__ int   g_flag0[SEQ];
__device__ int   g_flag1[SEQ];

// ---------------------------------------------------------------- helpers
__device__ __forceinline__ int ld_acq(const int* p) {
    int v;
    asm volatile("ld.acquire.gpu.s32 %0, [%1];" : "=r"(v) : "l"(p) : "memory");
    return v;
}
__device__ __forceinline__ void red_release(int* p) {
    asm volatile("red.release.gpu.global.add.s32 [%0], 1;" :: "l"(p) : "memory");
}
__device__ __forceinline__ void wait_flag(const int* p, int target) {
    while (ld_acq(p) < target) {}
}
__device__ __forceinline__ u64 dup2(float x) {
    u64 r; asm("mov.b64 %0, {%1, %1};" : "=l"(r) : "f"(x)); return r;
}
__device__ __forceinline__ void fma2(u64& acc, u64 a, u64 b) {
    asm("fma.rn.f32x2 %0, %1, %2, %0;" : "+l"(acc) : "l"(a), "l"(b));
}
__device__ __forceinline__ float2 unp2(u64 v) {
    float2 f; asm("mov.b64 {%0, %1}, %2;" : "=f"(f.x), "=f"(f.y) : "l"(v)); return f;
}
__device__ __forceinline__ float fold2(u64 v) {
    float2 f = unp2(v); return f.x + f.y;
}
__device__ __forceinline__ void cp16(uint32_t s, const void* g) {
    asm volatile("cp.async.cg.shared.global [%0], [%1], 16;" :: "r"(s), "l"(g));
}
__device__ __forceinline__ void cp_commit() {
    asm volatile("cp.async.commit_group;" ::: "memory");
}
#define CP_WAIT(N) asm volatile("cp.async.wait_group %0;" :: "n"(N) : "memory")

#define HS0 516   // L0 full h row stride (floats) — stride%32=4: conflict-free
#define HS1 260   // L1 half-buffer row stride
#define WS0 516   // L0 wT row stride
#define WS1 1032  // L1 wT row stride (K=1024)
#define RSL 576   // red: floats per k-slice (16 bg * 36)
#define RBG 36    // red: floats per bg (32 + 4 pad)

// Stage one 256-k half of h (64 rows x 256 floats = 64KB). 16 cp16/thread.
__device__ __forceinline__ void stageL0(uint32_t s0, const float* src, int half, int tid) {
#pragma unroll
    for (int j = 0; j < 16; j++) {
        int id = tid + j * NTHR;            // 0..4095
        int b = id >> 6, kc = id & 63;
        cp16(s0 + (uint32_t)((b * HS0 + half * 256 + kc * 4) * 4),
             src + (size_t)b * HH + half * 256 + kc * 4);
    }
    cp_commit();
}

// Stage 256 k's (koff..+255) of h (64KB) into an L1 half-buffer. 16 cp16/thread.
__device__ __forceinline__ void stage260(uint32_t sbuf, const float* src, int koff, int tid) {
#pragma unroll
    for (int j = 0; j < 16; j++) {
        int id = tid + j * NTHR;
        int b = id >> 6, kc = id & 63;
        cp16(sbuf + (uint32_t)((b * HS1 + kc * 4) * 4),
             src + (size_t)b * HH + koff + kc * 4);
    }
    cp_commit();
}

// 16-k segment. 4 batches x 8 cols per thread, K-packed f32x2.
// acc[m*8+c] holds (sum_even, sum_odd). w loads broadcast within warp.
template<int WS>
__device__ __forceinline__ void seg16(u64* acc,
                                      const float* hr0, const float* hr1,
                                      const float* hr2, const float* hr3,
                                      const float* wk)
{
#pragma unroll
    for (int i = 0; i < 16; i += 4) {
        ulonglong2 ha = *(const ulonglong2*)(hr0 + i);
        ulonglong2 hb = *(const ulonglong2*)(hr1 + i);
        ulonglong2 hc = *(const ulonglong2*)(hr2 + i);
        ulonglong2 hd = *(const ulonglong2*)(hr3 + i);
#pragma unroll
        for (int c = 0; c < 8; c++) {
            ulonglong2 w = *(const ulonglong2*)(wk + c * WS + i);
            fma2(acc[c],      ha.x, w.x);  fma2(acc[c],      ha.y, w.y);
            fma2(acc[8 + c],  hb.x, w.x);  fma2(acc[8 + c],  hb.y, w.y);
            fma2(acc[16 + c], hc.x, w.x);  fma2(acc[16 + c], hc.y, w.y);
            fma2(acc[24 + c], hd.x, w.x);  fma2(acc[24 + c], hd.y, w.y);
        }
    }
}

// Fold 32 u64 partials to floats and store to red[ks][bg][32] (36-padded).
__device__ __forceinline__ void store_partials(float* redf, const u64* acc,
                                               int ks, int bg) {
    float tmp[32];
#pragma unroll
    for (int j = 0; j < 32; j++) tmp[j] = fold2(acc[j]);
    float* wr = redf + (size_t)ks * RSL + (size_t)bg * RBG;
#pragma unroll
    for (int j = 0; j < 8; j++)
        *(float4*)(wr + 4 * j) = make_float4(tmp[4*j], tmp[4*j+1], tmp[4*j+2], tmp[4*j+3]);
}

// Reduce 16 k-slices for output (b=ob, cols och*4..+3).
__device__ __forceinline__ float4 reduce_outputs(const float* redf, int ob, int och) {
    const float* rp = redf + (size_t)(ob & 15) * RBG + (size_t)(ob >> 4) * 8 + och * 4;
    float4 s = make_float4(0.f, 0.f, 0.f, 0.f);
#pragma unroll
    for (int ks = 0; ks < 16; ks++) {
        float4 p = *(const float4*)(rp + (size_t)ks * RSL);
        s.x += p.x; s.y += p.y; s.z += p.z; s.w += p.w;
    }
    return s;
}

// ---------------------------------------------------------------------------
// Precompute Z0 = X @ Wx0 + bx0 + bh0 + zero the flags.
// ---------------------------------------------------------------------------
__global__ __launch_bounds__(256) void precompute_z0(
    const float* __restrict__ X,
    const float* __restrict__ W,
    const float* __restrict__ bxv,
    const float* __restrict__ bhv)
{
    __shared__ float As[16][64];
    __shared__ float Bs[16][64];
    const int tid = threadIdx.x;

    if (blockIdx.y == 0 && blockIdx.x < 4) {
        int i = blockIdx.x * 256 + tid;
        g_flag0[i] = 0;
        g_flag1[i] = 0;
    }

    const int tx = tid & 15;
    const int ty = tid >> 4;
    const int m0 = blockIdx.x * 64;
    const int n0 = blockIdx.y * 64;
    const int lm = tid >> 2;
    const int lk = (tid & 3) << 2;
    const int lr = tid >> 4;
    const int lc = (tid & 15) << 2;

    u64 acc[4][2];
#pragma unroll
    for (int i = 0; i < 4; i++) { acc[i][0] = 0ULL; acc[i][1] = 0ULL; }

    for (int kc = 0; kc < DD; kc += 16) {
        float4 a4 = *(const float4*)(X + (size_t)(m0 + lm) * DD + kc + lk);
        float4 b4 = *(const float4*)(W + (size_t)(kc + lr) * HH + n0 + lc);
        As[lk + 0][lm] = a4.x;
        As[lk + 1][lm] = a4.y;
        As[lk + 2][lm] = a4.z;
        As[lk + 3][lm] = a4.w;
        *(float4*)&Bs[lr][lc] = b4;
        __syncthreads();
#pragma unroll
        for (int kk = 0; kk < 16; kk++) {
            float4 av = *(const float4*)&As[kk][ty << 2];
            ulonglong2 bq = *(const ulonglong2*)&Bs[kk][tx << 2];
            u64 d;
            d = dup2(av.x); fma2(acc[0][0], d, bq.x); fma2(acc[0][1], d, bq.y);
            d = dup2(av.y); fma2(acc[1][0], d, bq.x); fma2(acc[1][1], d, bq.y);
            d = dup2(av.z); fma2(acc[2][0], d, bq.x); fma2(acc[2][1], d, bq.y);
            d = dup2(av.w); fma2(acc[3][0], d, bq.x); fma2(acc[3][1], d, bq.y);
        }
        __syncthreads();
    }
    const int n = n0 + (tx << 2);
    float4 bx4 = *(const float4*)(bxv + n);
    float4 bh4 = *(const float4*)(bhv + n);
#pragma unroll
    for (int i = 0; i < 4; i++) {
        int m = m0 + (ty << 2) + i;
        float2 c0 = unp2(acc[i][0]);
        float2 c1 = unp2(acc[i][1]);
        float4 o;
        o.x = c0.x + bx4.x + bh4.x;
        o.y = c0.y + bx4.y + bh4.y;
        o.z = c1.x + bx4.z + bh4.z;
        o.w = c1.y + bx4.w + bh4.w;
        *(float4*)(g_z0 + (size_t)m * HH + n) = o;
    }
}

// ---------------------------------------------------------------------------
// Persistent sequential kernel. 128 CTAs (1/SM), 256 threads (8 warps).
//   blocks [0,64):   layer 0, 8 cols, K=512
//   blocks [64,128): layer 1, 8 cols, K=1024 concat [h1[t-1]; h0[t]]
// Thread: bg=tid&15 (4 batches stride 16), ks=tid>>4 (16 k-slices of 16k per
// 256-chunk). Partials folded to f32, 36-padded reduction. cp.async chunks
// overlap staging with compute; 8 warps hide LDS/issue latency.
// ---------------------------------------------------------------------------
__global__ __launch_bounds__(NTHR) void rnn_seq(
    const float* __restrict__ h_init,
    const float* __restrict__ Wh0,
    const float* __restrict__ Wx1,
    const float* __restrict__ bx1,
    const float* __restrict__ Wh1,
    const float* __restrict__ bh1,
    float* __restrict__ out)
{
    extern __shared__ float sm[];
    const int tid = threadIdx.x;
    const int bg  = tid & 15;       // batch group
    const int ks  = tid >> 4;       // k-slice 0..15
    const int ko  = ks * 16;        // k offset within 256-chunk
    const int ob  = tid & 63;       // output batch (reducers: tid<128)
    const int och = (tid >> 6) & 1; // output col half

    if (blockIdx.x < NCTA0) {
        // ------------------------- layer 0 -------------------------
        const int n0 = blockIdx.x * 8;
        float* hs   = sm;                       // [64][HS0] = 33024 f
        float* wsT  = sm + 64 * HS0;            // [8][WS0]  = 4128 f
        float* redf = wsT + 8 * WS0;            // [16][RSL] = 9216 f
        const uint32_t s0 = (uint32_t)__cvta_generic_to_shared(hs);

        for (int i = tid; i < 1024; i += NTHR) {
            int k = i >> 1, cq = i & 1;
            float4 v = *(const float4*)(Wh0 + (size_t)k * HH + n0 + cq * 4);
            wsT[(cq * 4 + 0) * WS0 + k] = v.x;
            wsT[(cq * 4 + 1) * WS0 + k] = v.y;
            wsT[(cq * 4 + 2) * WS0 + k] = v.z;
            wsT[(cq * 4 + 3) * WS0 + k] = v.w;
        }
        __syncthreads();

        const float* hr0 = hs + (bg +  0) * HS0 + ko;
        const float* hr1 = hs + (bg + 16) * HS0 + ko;
        const float* hr2 = hs + (bg + 32) * HS0 + ko;
        const float* hr3 = hs + (bg + 48) * HS0 + ko;

        for (int t = 0; t < SEQ; t++) {
            const float* zp = g_z0 + (size_t)t * BH + (size_t)ob * HH + n0 + och * 4;
            float4 zv = *(const float4*)zp;

            if (t > 0) wait_flag(&g_flag0[t - 1], NCTA0);
            const float* hp = (t == 0) ? h_init : (g_h0 + (size_t)(t - 1) * BH);
            stageL0(s0, hp, 0, tid);
            stageL0(s0, hp, 1, tid);

            u64 acc[32];
#pragma unroll
            for (int i = 0; i < 32; i++) acc[i] = 0ULL;

            CP_WAIT(1); __syncthreads();
            seg16<WS0>(acc, hr0, hr1, hr2, hr3, wsT + ko);
            CP_WAIT(0); __syncthreads();
            seg16<WS0>(acc, hr0 + 256, hr1 + 256, hr2 + 256, hr3 + 256,
                       wsT + 256 + ko);

            store_partials(redf, acc, ks, bg);
            __syncthreads();
            if (tid < 128) {
                float4 r = reduce_outputs(redf, ob, och);
                float4 v;
                v.x = tanhf(r.x + zv.x); v.y = tanhf(r.y + zv.y);
                v.z = tanhf(r.z + zv.z); v.w = tanhf(r.w + zv.w);
                *(float4*)(g_h0 + (size_t)t * BH + (size_t)ob * HH + n0 + och * 4) = v;
                if (t == SEQ - 1)
                    *(float4*)(out + (size_t)SEQ * BH + (size_t)ob * HH + n0 + och * 4) = v;
            }
            __syncthreads();
            if (tid == 0) red_release(&g_flag0[t]);
        }
    } else {
        // ------------------------- layer 1 -------------------------
        const int n0 = (blockIdx.x - NCTA0) * 8;
        float* buf0 = sm;                       // [64][HS1] = 16640 f
        float* buf1 = sm + 64 * HS1;            // 16640 f
        float* wsT  = sm + 2 * 64 * HS1;        // [8][WS1] = 8256 f
        float* redf = wsT + 8 * WS1;            // 9216 f
        const uint32_t sb0 = (uint32_t)__cvta_generic_to_shared(buf0);
        const uint32_t sb1 = (uint32_t)__cvta_generic_to_shared(buf1);

        for (int i = tid; i < 1024; i += NTHR) {
            int k = i >> 1, cq = i & 1;
            float4 vh = *(const float4*)(Wh1 + (size_t)k * HH + n0 + cq * 4);
            float4 vx = *(const float4*)(Wx1 + (size_t)k * HH + n0 + cq * 4);
            wsT[(cq * 4 + 0) * WS1 + k] = vh.x;
            wsT[(cq * 4 + 1) * WS1 + k] = vh.y;
            wsT[(cq * 4 + 2) * WS1 + k] = vh.z;
            wsT[(cq * 4 + 3) * WS1 + k] = vh.w;
            wsT[(cq * 4 + 0) * WS1 + 512 + k] = vx.x;
            wsT[(cq * 4 + 1) * WS1 + 512 + k] = vx.y;
            wsT[(cq * 4 + 2) * WS1 + 512 + k] = vx.z;
            wsT[(cq * 4 + 3) * WS1 + 512 + k] = vx.w;
        }
        float4 bias;
        {
            const float* bx = bx1 + n0 + och * 4;
            const float* bh = bh1 + n0 + och * 4;
            bias.x = bx[0] + bh[0]; bias.y = bx[1] + bh[1];
            bias.z = bx[2] + bh[2]; bias.w = bx[3] + bh[3];
        }
        __syncthreads();

        const int bo0 = (bg +  0) * HS1 + ko, bo1 = (bg + 16) * HS1 + ko;
        const int bo2 = (bg + 32) * HS1 + ko, bo3 = (bg + 48) * HS1 + ko;

        for (int t = 0; t < SEQ; t++) {
            if (t > 0) wait_flag(&g_flag1[t - 1], NCTA1);
            const float* h1src = (t == 0) ? (h_init + BH) : (out + (size_t)(t - 1) * BH);

            stage260(sb0, h1src, 0, tid);     // A0
            stage260(sb1, h1src, 256, tid);   // A1

            u64 acc[32];
#pragma unroll
            for (int i = 0; i < 32; i++) acc[i] = 0ULL;

            CP_WAIT(1); __syncthreads();
            seg16<WS1>(acc, buf0 + bo0, buf0 + bo1, buf0 + bo2, buf0 + bo3,
                       wsT + ko);
            CP_WAIT(0); __syncthreads();      // A1 ready, buf0 consumed

            wait_flag(&g_flag0[t], NCTA0);
            const float* h0src = g_h0 + (size_t)t * BH;
            stage260(sb0, h0src, 0, tid);     // B0

            seg16<WS1>(acc, buf1 + bo0, buf1 + bo1, buf1 + bo2, buf1 + bo3,
                       wsT + 256 + ko);
            CP_WAIT(0); __syncthreads();      // B0 ready, buf1 consumed

            stage260(sb1, h0src, 256, tid);   // B1

            seg16<WS1>(acc, buf0 + bo0, buf0 + bo1, buf0 + bo2, buf0 + bo3,
                       wsT + 512 + ko);
            CP_WAIT(0); __syncthreads();      // B1 ready, buf0 consumed

            seg16<WS1>(acc, buf1 + bo0, buf1 + bo1, buf1 + bo2, buf1 + bo3,
                       wsT + 768 + ko);

            store_partials(redf, acc, ks, bg);
            __syncthreads();
            if (tid < 128) {
                float4 r = reduce_outputs(redf, ob, och);
                float4 v;
                v.x = tanhf(r.x + bias.x); v.y = tanhf(r.y + bias.y);
                v.z = tanhf(r.z + bias.z); v.w = tanhf(r.w + bias.w);
                *(float4*)(out + (size_t)t * BH + (size_t)ob * HH + n0 + och * 4) = v;
                if (t == SEQ - 1)
                    *(float4*)(out + (size_t)SEQ * BH + BH + (size_t)ob * HH + n0 + och * 4) = v;
            }
            __syncthreads();
            if (tid == 0) red_release(&g_flag1[t]);
        }
    }
}

// L1: (2*64*260 + 8*1032 + 16*576)*4 = (33280+8256+9216)*4 = 203008 B
// L0: (64*516 + 8*516 + 16*576)*4   = (33024+4128+9216)*4 = 185472 B
#define SMEM_BYTES 203008

extern "C" void kernel_launch(void* const* d_in, const int* in_sizes, int n_in,
                              void* d_out, int out_size)
{
    const float* x   = (const float*)d_in[0];
    const float* h0  = (const float*)d_in[1];
    const float* Wx0 = (const float*)d_in[2];
    const float* bx0 = (const float*)d_in[3];
    const float* Wh0 = (const float*)d_in[4];
    const float* bh0 = (const float*)d_in[5];
    const float* Wx1 = (const float*)d_in[6];
    const float* bx1 = (const float*)d_in[7];
    const float* Wh1 = (const float*)d_in[8];
    const float* bh1 = (const float*)d_in[9];
    float* out = (float*)d_out;
    (void)in_sizes; (void)n_in; (void)out_size;

    dim3 gz((SEQ * BB) / 64, HH / 64);
    precompute_z0<<<gz, 256>>>(x, Wx0, bx0, bh0);

    static int attr_set = 0;
    if (!attr_set) {
        cudaFuncSetAttribute(rnn_seq, cudaFuncAttributeMaxDynamicSharedMemorySize,
                             SMEM_BYTES);
        attr_set = 1;
    }
    rnn_seq<<<NCTA0 + NCTA1, NTHR, SMEM_BYTES>>>(h0, Wh0, Wx1, bx1, Wh1, bh1, out);
}

// round 9
// speedup vs baseline: 1.5578x; 1.0118x over previous
#include <cuda_runtime.h>
#include <math.h>
#include <stdint.h>

#define SEQ 1024
#define BB  64
#define DD  512
#define HH  512
#define BH  (BB * HH)

#define NCTA0 64   // layer-0 CTAs, 8 cols each
#define NCTA1 64   // layer-1 CTAs, 8 cols each
#define NTHR  256

typedef unsigned long long u64;

// Scratch (allocation-free rule: __device__ globals)
__device__ float g_z0[SEQ * BB * HH];   // x@Wx0 + bx0 + bh0 (b-major)
__device__ float g_h0[SEQ * BB * HH];   // layer-0 hidden history (b-major)
__device__ int   g_flag0[SEQ];
__device__ int   g_flag1[SEQ];

// ---------------------------------------------------------------- helpers
__device__ __forceinline__ int ld_acq(const int* p) {
    int v;
    asm volatile("ld.acquire.gpu.s32 %0, [%1];" : "=r"(v) : "l"(p) : "memory");
    return v;
}
__device__ __forceinline__ void red_release(int* p) {
    asm volatile("red.release.gpu.global.add.s32 [%0], 1;" :: "l"(p) : "memory");
}
__device__ __forceinline__ void wait_flag(const int* p, int target) {
    while (ld_acq(p) < target) {}
}
__device__ __forceinline__ u64 dup2(float x) {
    u64 r; asm("mov.b64 %0, {%1, %1};" : "=l"(r) : "f"(x)); return r;
}
__device__ __forceinline__ void fma2(u64& acc, u64 a, u64 b) {
    asm("fma.rn.f32x2 %0, %1, %2, %0;" : "+l"(acc) : "l"(a), "l"(b));
}
__device__ __forceinline__ float2 unp2(u64 v) {
    float2 f; asm("mov.b64 {%0, %1}, %2;" : "=f"(f.x), "=f"(f.y) : "l"(v)); return f;
}
__device__ __forceinline__ float fold2(u64 v) {
    float2 f = unp2(v); return f.x + f.y;
}
__device__ __forceinline__ void cp16(uint32_t s, const void* g) {
    asm volatile("cp.async.cg.shared.global [%0], [%1], 16;" :: "r"(s), "l"(g));
}
__device__ __forceinline__ void cp_commit() {
    asm volatile("cp.async.commit_group;" ::: "memory");
}
#define CP_WAIT(N) asm volatile("cp.async.wait_group %0;" :: "n"(N) : "memory")

#define HS0 516     // L0 h row stride (floats); %32==4 → conflict-free phases
#define HS1 132     // L1 ring-slot row stride (128k chunk + pad); %32==4
#define SLOT (64 * HS1)   // 8448 floats per ring slot
#define WS0 516     // L0 wT row stride
#define WS1 1032    // L1 wT row stride (K=1024)
#define RSL 576     // red: floats per k-slice (16 bg * 36)
#define RBG 36      // red: floats per bg (32 + 4 pad)

// Stage one 128-k chunk (64 rows x 128 floats = 32KB). 8 cp16/thread.
// L0 flavor: into flat hs at column c*128.
__device__ __forceinline__ void stage_chunkL0(uint32_t s0, const float* src,
                                              int c, int tid) {
#pragma unroll
    for (int j = 0; j < 8; j++) {
        int id = tid + j * NTHR;            // 0..2047
        int b = id >> 5, kc = id & 31;
        cp16(s0 + (uint32_t)((b * HS0 + c * 128 + kc * 4) * 4),
             src + (size_t)b * HH + c * 128 + kc * 4);
    }
    cp_commit();
}
// L1 flavor: k's [koff, koff+128) into a ring slot.
__device__ __forceinline__ void stage_slot(uint32_t sdst, const float* src,
                                           int koff, int tid) {
#pragma unroll
    for (int j = 0; j < 8; j++) {
        int id = tid + j * NTHR;
        int b = id >> 5, kc = id & 31;
        cp16(sdst + (uint32_t)((b * HS1 + kc * 4) * 4),
             src + (size_t)b * HH + koff + kc * 4);
    }
    cp_commit();
}

// 8-k segment. 4 batches x 8 cols per thread, K-packed f32x2.
// acc[m*8+c] holds (sum_even, sum_odd). w loads broadcast within warp.
template<int WS>
__device__ __forceinline__ void seg8(u64* acc,
                                     const float* hr0, const float* hr1,
                                     const float* hr2, const float* hr3,
                                     const float* wk)
{
#pragma unroll
    for (int i = 0; i < 8; i += 4) {
        ulonglong2 ha = *(const ulonglong2*)(hr0 + i);
        ulonglong2 hb = *(const ulonglong2*)(hr1 + i);
        ulonglong2 hc = *(const ulonglong2*)(hr2 + i);
        ulonglong2 hd = *(const ulonglong2*)(hr3 + i);
#pragma unroll
        for (int c = 0; c < 8; c++) {
            ulonglong2 w = *(const ulonglong2*)(wk + c * WS + i);
            fma2(acc[c],      ha.x, w.x);  fma2(acc[c],      ha.y, w.y);
            fma2(acc[8 + c],  hb.x, w.x);  fma2(acc[8 + c],  hb.y, w.y);
            fma2(acc[16 + c], hc.x, w.x);  fma2(acc[16 + c], hc.y, w.y);
            fma2(acc[24 + c], hd.x, w.x);  fma2(acc[24 + c], hd.y, w.y);
        }
    }
}

// Fold 32 u64 partials to floats and store to red[ks][bg][32] (36-padded).
__device__ __forceinline__ void store_partials(float* redf, const u64* acc,
                                               int ks, int bg) {
    float tmp[32];
#pragma unroll
    for (int j = 0; j < 32; j++) tmp[j] = fold2(acc[j]);
    float* wr = redf + (size_t)ks * RSL + (size_t)bg * RBG;
#pragma unroll
    for (int j = 0; j < 8; j++)
        *(float4*)(wr + 4 * j) = make_float4(tmp[4*j], tmp[4*j+1], tmp[4*j+2], tmp[4*j+3]);
}

// Reduce 16 k-slices for output (b=ob, cols och*4..+3).
__device__ __forceinline__ float4 reduce_outputs(const float* redf, int ob, int och) {
    const float* rp = redf + (size_t)(ob & 15) * RBG + (size_t)(ob >> 4) * 8 + och * 4;
    float4 s = make_float4(0.f, 0.f, 0.f, 0.f);
#pragma unroll
    for (int ks = 0; ks < 16; ks++) {
        float4 p = *(const float4*)(rp + (size_t)ks * RSL);
        s.x += p.x; s.y += p.y; s.z += p.z; s.w += p.w;
    }
    return s;
}

// ---------------------------------------------------------------------------
// Precompute Z0 = X @ Wx0 + bx0 + bh0 + zero the flags.
// ---------------------------------------------------------------------------
__global__ __launch_bounds__(256) void precompute_z0(
    const float* __restrict__ X,
    const float* __restrict__ W,
    const float* __restrict__ bxv,
    const float* __restrict__ bhv)
{
    __shared__ float As[16][64];
    __shared__ float Bs[16][64];
    const int tid = threadIdx.x;

    if (blockIdx.y == 0 && blockIdx.x < 4) {
        int i = blockIdx.x * 256 + tid;
        g_flag0[i] = 0;
        g_flag1[i] = 0;
    }

    const int tx = tid & 15;
    const int ty = tid >> 4;
    const int m0 = blockIdx.x * 64;
    const int n0 = blockIdx.y * 64;
    const int lm = tid >> 2;
    const int lk = (tid & 3) << 2;
    const int lr = tid >> 4;
    const int lc = (tid & 15) << 2;

    u64 acc[4][2];
#pragma unroll
    for (int i = 0; i < 4; i++) { acc[i][0] = 0ULL; acc[i][1] = 0ULL; }

    for (int kc = 0; kc < DD; kc += 16) {
        float4 a4 = *(const float4*)(X + (size_t)(m0 + lm) * DD + kc + lk);
        float4 b4 = *(const float4*)(W + (size_t)(kc + lr) * HH + n0 + lc);
        As[lk + 0][lm] = a4.x;
        As[lk + 1][lm] = a4.y;
        As[lk + 2][lm] = a4.z;
        As[lk + 3][lm] = a4.w;
        *(float4*)&Bs[lr][lc] = b4;
        __syncthreads();
#pragma unroll
        for (int kk = 0; kk < 16; kk++) {
            float4 av = *(const float4*)&As[kk][ty << 2];
            ulonglong2 bq = *(const ulonglong2*)&Bs[kk][tx << 2];
            u64 d;
            d = dup2(av.x); fma2(acc[0][0], d, bq.x); fma2(acc[0][1], d, bq.y);
            d = dup2(av.y); fma2(acc[1][0], d, bq.x); fma2(acc[1][1], d, bq.y);
            d = dup2(av.z); fma2(acc[2][0], d, bq.x); fma2(acc[2][1], d, bq.y);
            d = dup2(av.w); fma2(acc[3][0], d, bq.x); fma2(acc[3][1], d, bq.y);
        }
        __syncthreads();
    }
    const int n = n0 + (tx << 2);
    float4 bx4 = *(const float4*)(bxv + n);
    float4 bh4 = *(const float4*)(bhv + n);
#pragma unroll
    for (int i = 0; i < 4; i++) {
        int m = m0 + (ty << 2) + i;
        float2 c0 = unp2(acc[i][0]);
        float2 c1 = unp2(acc[i][1]);
        float4 o;
        o.x = c0.x + bx4.x + bh4.x;
        o.y = c0.y + bx4.y + bh4.y;
        o.z = c1.x + bx4.z + bh4.z;
        o.w = c1.y + bx4.w + bh4.w;
        *(float4*)(g_z0 + (size_t)m * HH + n) = o;
    }
}

// ---------------------------------------------------------------------------
// Persistent sequential kernel. 128 CTAs (1/SM), 256 threads (8 warps).
//   blocks [0,64):   layer 0, 8 cols, K=512; 4 x 128k cp.async chunks.
//   blocks [64,128): layer 1, 8 cols, K=1024 concat — phase B (h0[t]@Wx1)
//                    FIRST (hides flag1 wait), then phase A (h1[t-1]@Wh1).
//                    4-slot ring; A staged into slots as B consumes them.
// Thread: bg=tid&15 (4 batches stride 16), ks=tid>>4 → 8k per chunk.
// ---------------------------------------------------------------------------
__global__ __launch_bounds__(NTHR) void rnn_seq(
    const float* __restrict__ h_init,
    const float* __restrict__ Wh0,
    const float* __restrict__ Wx1,
    const float* __restrict__ bx1,
    const float* __restrict__ Wh1,
    const float* __restrict__ bh1,
    float* __restrict__ out)
{
    extern __shared__ float sm[];
    const int tid = threadIdx.x;
    const int bg  = tid & 15;
    const int ks  = tid >> 4;        // 0..15
    const int kio = ks * 8;          // k offset inside a 128-chunk
    const int ob  = tid & 63;
    const int och = (tid >> 6) & 1;

    if (blockIdx.x < NCTA0) {
        // ------------------------- layer 0 -------------------------
        const int n0 = blockIdx.x * 8;
        float* hs   = sm;                       // [64][HS0]
        float* wsT  = sm + 64 * HS0;            // [8][WS0]
        float* redf = wsT + 8 * WS0;            // [16][RSL]
        const uint32_t s0 = (uint32_t)__cvta_generic_to_shared(hs);

        for (int i = tid; i < 1024; i += NTHR) {
            int k = i >> 1, cq = i & 1;
            float4 v = *(const float4*)(Wh0 + (size_t)k * HH + n0 + cq * 4);
            wsT[(cq * 4 + 0) * WS0 + k] = v.x;
            wsT[(cq * 4 + 1) * WS0 + k] = v.y;
            wsT[(cq * 4 + 2) * WS0 + k] = v.z;
            wsT[(cq * 4 + 3) * WS0 + k] = v.w;
        }
        __syncthreads();

        const int bo0 = (bg +  0) * HS0 + kio, bo1 = (bg + 16) * HS0 + kio;
        const int bo2 = (bg + 32) * HS0 + kio, bo3 = (bg + 48) * HS0 + kio;

        for (int t = 0; t < SEQ; t++) {
            const float* zp = g_z0 + (size_t)t * BH + (size_t)ob * HH + n0 + och * 4;
            float4 zv = *(const float4*)zp;

            if (t > 0 && tid == 0) wait_flag(&g_flag0[t - 1], NCTA0);
            __syncthreads();
            const float* hp = (t == 0) ? h_init : (g_h0 + (size_t)(t - 1) * BH);
            stage_chunkL0(s0, hp, 0, tid);
            stage_chunkL0(s0, hp, 1, tid);
            stage_chunkL0(s0, hp, 2, tid);
            stage_chunkL0(s0, hp, 3, tid);

            u64 acc[32];
#pragma unroll
            for (int i = 0; i < 32; i++) acc[i] = 0ULL;

#pragma unroll
            for (int c = 0; c < 4; c++) {
                if (c == 0) { CP_WAIT(3); } else if (c == 1) { CP_WAIT(2); }
                else if (c == 2) { CP_WAIT(1); } else { CP_WAIT(0); }
                __syncthreads();
                const int co = c * 128;
                seg8<WS0>(acc, hs + bo0 + co, hs + bo1 + co,
                          hs + bo2 + co, hs + bo3 + co, wsT + co + kio);
            }

            store_partials(redf, acc, ks, bg);
            __syncthreads();
            if (tid < 128) {
                float4 r = reduce_outputs(redf, ob, och);
                float4 v;
                v.x = tanhf(r.x + zv.x); v.y = tanhf(r.y + zv.y);
                v.z = tanhf(r.z + zv.z); v.w = tanhf(r.w + zv.w);
                *(float4*)(g_h0 + (size_t)t * BH + (size_t)ob * HH + n0 + och * 4) = v;
                if (t == SEQ - 1)
                    *(float4*)(out + (size_t)SEQ * BH + (size_t)ob * HH + n0 + och * 4) = v;
            }
            __syncthreads();
            if (tid == 0) red_release(&g_flag0[t]);
        }
    } else {
        // ------------------------- layer 1 -------------------------
        const int n0 = (blockIdx.x - NCTA0) * 8;
        float* ring = sm;                       // 4 slots x [64][HS1]
        float* wsT  = sm + 4 * SLOT;            // [8][WS1]: 0..511 Wh1, 512..1023 Wx1
        float* redf = wsT + 8 * WS1;            // [16][RSL]
        uint32_t sslot[4];
#pragma unroll
        for (int s = 0; s < 4; s++)
            sslot[s] = (uint32_t)__cvta_generic_to_shared(ring + s * SLOT);

        for (int i = tid; i < 1024; i += NTHR) {
            int k = i >> 1, cq = i & 1;
            float4 vh = *(const float4*)(Wh1 + (size_t)k * HH + n0 + cq * 4);
            float4 vx = *(const float4*)(Wx1 + (size_t)k * HH + n0 + cq * 4);
            wsT[(cq * 4 + 0) * WS1 + k] = vh.x;
            wsT[(cq * 4 + 1) * WS1 + k] = vh.y;
            wsT[(cq * 4 + 2) * WS1 + k] = vh.z;
            wsT[(cq * 4 + 3) * WS1 + k] = vh.w;
            wsT[(cq * 4 + 0) * WS1 + 512 + k] = vx.x;
            wsT[(cq * 4 + 1) * WS1 + 512 + k] = vx.y;
            wsT[(cq * 4 + 2) * WS1 + 512 + k] = vx.z;
            wsT[(cq * 4 + 3) * WS1 + 512 + k] = vx.w;
        }
        float4 bias;
        {
            const float* bx = bx1 + n0 + och * 4;
            const float* bh = bh1 + n0 + och * 4;
            bias.x = bx[0] + bh[0]; bias.y = bx[1] + bh[1];
            bias.z = bx[2] + bh[2]; bias.w = bx[3] + bh[3];
        }
        __syncthreads();

        const int bo0 = (bg +  0) * HS1 + kio, bo1 = (bg + 16) * HS1 + kio;
        const int bo2 = (bg + 32) * HS1 + kio, bo3 = (bg + 48) * HS1 + kio;

        for (int t = 0; t < SEQ; t++) {
            // ---- phase B first: h0[t] @ Wx1 (L0 runs ahead; flag0 cheap) ----
            if (tid == 0) wait_flag(&g_flag0[t], NCTA0);
            __syncthreads();
            const float* h0src = g_h0 + (size_t)t * BH;
            stage_slot(sslot[0], h0src, 0,   tid);
            stage_slot(sslot[1], h0src, 128, tid);
            stage_slot(sslot[2], h0src, 256, tid);
            stage_slot(sslot[3], h0src, 384, tid);

            const float* h1src = (t == 0) ? (h_init + BH)
                                          : (out + (size_t)(t - 1) * BH);
            u64 acc[32];
#pragma unroll
            for (int i = 0; i < 32; i++) acc[i] = 0ULL;

            // B chunk 0 (wT cols 512..639)
            CP_WAIT(3); __syncthreads();
            seg8<WS1>(acc, ring + bo0, ring + bo1, ring + bo2, ring + bo3,
                      wsT + 512 + kio);
            // poll for h1[t-1] while B still has work queued
            if (tid == 0) wait_flag(&g_flag1[t - 1] - ((t == 0) ? 1 : 0),
                                    (t == 0) ? 0 : NCTA1);   // t==0: no wait
            CP_WAIT(2); __syncthreads();           // b1 ready; slot0 free
            stage_slot(sslot[0], h1src, 0, tid);   // A chunk 0
#pragma unroll
            for (int c = 1; c < 4; c++) {          // B chunks 1..3
                const float* sp = ring + c * SLOT;
                seg8<WS1>(acc, sp + bo0, sp + bo1, sp + bo2, sp + bo3,
                          wsT + 512 + c * 128 + kio);
                CP_WAIT(2); __syncthreads();       // next data ready; slot c free
                stage_slot(sslot[c], h1src, c * 128, tid);  // A chunk c
            }
            // A chunks 0..3 (wT cols 0..511)
#pragma unroll
            for (int c = 0; c < 4; c++) {
                const float* sp = ring + c * SLOT;
                seg8<WS1>(acc, sp + bo0, sp + bo1, sp + bo2, sp + bo3,
                          wsT + c * 128 + kio);
                if (c < 3) {
                    if (c == 0) { CP_WAIT(2); } else if (c == 1) { CP_WAIT(1); }
                    else { CP_WAIT(0); }
                    __syncthreads();
                }
            }

            store_partials(redf, acc, ks, bg);
            __syncthreads();
            if (tid < 128) {
                float4 r = reduce_outputs(redf, ob, och);
                float4 v;
                v.x = tanhf(r.x + bias.x); v.y = tanhf(r.y + bias.y);
                v.z = tanhf(r.z + bias.z); v.w = tanhf(r.w + bias.w);
                *(float4*)(out + (size_t)t * BH + (size_t)ob * HH + n0 + och * 4) = v;
                if (t == SEQ - 1)
                    *(float4*)(out + (size_t)SEQ * BH + BH + (size_t)ob * HH + n0 + och * 4) = v;
            }
            __syncthreads();
            if (tid == 0) red_release(&g_flag1[t]);
        }
    }
}

// L1: (4*8448 + 8*1032 + 16*576)*4 = (33792+8256+9216)*4 = 205056 B
// L0: (64*516 + 8*516 + 16*576)*4  = (33024+4128+9216)*4 = 185472 B
#define SMEM_BYTES 205056

extern "C" void kernel_launch(void* const* d_in, const int* in_sizes, int n_in,
                              void* d_out, int out_size)
{
    const float* x   = (const float*)d_in[0];
    const float* h0  = (const float*)d_in[1];
    const float* Wx0 = (const float*)d_in[2];
    const float* bx0 = (const float*)d_in[3];
    const float* Wh0 = (const float*)d_in[4];
    const float* bh0 = (const float*)d_in[5];
    const float* Wx1 = (const float*)d_in[6];
    const float* bx1 = (const float*)d_in[7];
    const float* Wh1 = (const float*)d_in[8];
    const float* bh1 = (const float*)d_in[9];
    float* out = (float*)d_out;
    (void)in_sizes; (void)n_in; (void)out_size;

    dim3 gz((SEQ * BB) / 64, HH / 64);
    precompute_z0<<<gz, 256>>>(x, Wx0, bx0, bh0);

    static int attr_set = 0;
    if (!attr_set) {
        cudaFuncSetAttribute(rnn_seq, cudaFuncAttributeMaxDynamicSharedMemorySize,
                             SMEM_BYTES);
        attr_set = 1;
    }
    rnn_seq<<<NCTA0 + NCTA1, NTHR, SMEM_BYTES>>>(h0, Wh0, Wx1, bx1, Wh1, bh1, out);
}